// round 4
// baseline (speedup 1.0000x reference)
#include <cuda_runtime.h>
#include <math.h>

struct C2 { float r, i; };
__device__ __forceinline__ C2 cmul(C2 a, C2 b) {
    return { a.r * b.r - a.i * b.i, a.r * b.i + a.i * b.r };
}
__device__ __forceinline__ C2 cadd(C2 a, C2 b) { return { a.r + b.r, a.i + b.i }; }

__device__ __forceinline__ void mm2(const C2 A[2][2], const C2 B[2][2], C2 O[2][2]) {
#pragma unroll
    for (int r = 0; r < 2; r++)
#pragma unroll
        for (int c = 0; c < 2; c++)
            O[r][c] = cadd(cmul(A[r][0], B[0][c]), cmul(A[r][1], B[1][c]));
}

// U_layer = RZ(w2) @ RY(w1) @ RX(w0)
__device__ __forceinline__ void layer_unitary(float w0, float w1, float w2, C2 U[2][2]) {
    float c0, s0, c1, s1, c2, s2;
    sincosf(0.5f * w0, &s0, &c0);
    sincosf(0.5f * w1, &s1, &c1);
    sincosf(0.5f * w2, &s2, &c2);
    C2 rx[2][2] = { { {c0, 0.f}, {0.f, -s0} }, { {0.f, -s0}, {c0, 0.f} } };
    C2 ry[2][2] = { { {c1, 0.f}, {-s1, 0.f} }, { {s1, 0.f}, {c1, 0.f} } };
    C2 rz[2][2] = { { {c2, -s2}, {0.f, 0.f} }, { {0.f, 0.f}, {c2, s2} } };
    C2 t[2][2];
    mm2(ry, rx, t);
    mm2(rz, t, U);
}

// Collapse the whole circuit:
//   z = alpha*cos(x) + beta*sin(x) = R*cos(x - phi)
//   out = (a*R) * cos(x - phi) + b
__device__ __forceinline__ void compute_coefs(const float* __restrict__ weights,
                                              const float* __restrict__ a,
                                              const float* __restrict__ b,
                                              float& amp, float& phi, float& bb) {
    C2 U0[2][2], U1[2][2], U[2][2];
    layer_unitary(__ldg(weights + 0), __ldg(weights + 1), __ldg(weights + 2), U0);
    layer_unitary(__ldg(weights + 3), __ldg(weights + 4), __ldg(weights + 5), U1);
    mm2(U1, U0, U);

    float alpha = (U[0][0].r * U[0][0].r + U[0][0].i * U[0][0].i)
                - (U[1][0].r * U[1][0].r + U[1][0].i * U[1][0].i);
    float beta  = (U[0][0].r * U[0][1].r + U[0][0].i * U[0][1].i)
                - (U[1][0].r * U[1][1].r + U[1][0].i * U[1][1].i);

    float R = sqrtf(alpha * alpha + beta * beta);
    phi = (R > 0.f) ? atan2f(beta, alpha) : 0.f;
    amp = __ldg(a) * R;
    bb  = __ldg(b);
}

__device__ __forceinline__ float4 eval4(float4 v, float amp, float phi, float bb) {
    float4 o;
    o.x = fmaf(amp, __cosf(v.x - phi), bb);
    o.y = fmaf(amp, __cosf(v.y - phi), bb);
    o.z = fmaf(amp, __cosf(v.z - phi), bb);
    o.w = fmaf(amp, __cosf(v.w - phi), bb);
    return o;
}

__global__ void __launch_bounds__(256)
qpinn_fused(const float4* __restrict__ x4, float4* __restrict__ out4, int n4,
            const float* __restrict__ x, float* __restrict__ out, int n,
            const float* __restrict__ weights,
            const float* __restrict__ a, const float* __restrict__ b) {
    float amp, phi, bb;
    compute_coefs(weights, a, b, amp, phi, bb);

    const int stride = gridDim.x * blockDim.x;
    int idx = blockIdx.x * blockDim.x + threadIdx.x;

    // Main loop: 4 independent float4 loads in flight per iteration (MLP=4)
    for (; idx + 3 * stride < n4; idx += 4 * stride) {
        float4 v0 = __ldcs(x4 + idx);
        float4 v1 = __ldcs(x4 + idx + stride);
        float4 v2 = __ldcs(x4 + idx + 2 * stride);
        float4 v3 = __ldcs(x4 + idx + 3 * stride);
        __stcs(out4 + idx,              eval4(v0, amp, phi, bb));
        __stcs(out4 + idx + stride,     eval4(v1, amp, phi, bb));
        __stcs(out4 + idx + 2 * stride, eval4(v2, amp, phi, bb));
        __stcs(out4 + idx + 3 * stride, eval4(v3, amp, phi, bb));
    }
    // Remainder float4s
    for (; idx < n4; idx += stride) {
        __stcs(out4 + idx, eval4(__ldcs(x4 + idx), amp, phi, bb));
    }
    // Scalar tail (n not divisible by 4)
    int tail = n4 * 4 + (blockIdx.x * blockDim.x + threadIdx.x);
    if (tail < n) {
        __stcs(out + tail, fmaf(amp, __cosf(__ldcs(x + tail) - phi), bb));
    }
}

extern "C" void kernel_launch(void* const* d_in, const int* in_sizes, int n_in,
                              void* d_out, int out_size) {
    const float* x       = (const float*)d_in[0];
    const float* weights = (const float*)d_in[1];
    const float* a       = (const float*)d_in[2];
    const float* b       = (const float*)d_in[3];
    float* out = (float*)d_out;

    int n = in_sizes[0];
    int n4 = n / 4;

    const int threads = 256;
    // 4096 blocks * 256 threads * 4 float4 * 4 floats = 16,777,216 = N exactly.
    long long want = ((long long)n4 + threads * 4 - 1) / (threads * 4);
    int blocks = (int)want;
    if (blocks < 1) blocks = 1;
    if (blocks > 65535 * 32) blocks = 65535 * 32;

    qpinn_fused<<<blocks, threads>>>((const float4*)x, (float4*)out, n4,
                                     x, out, n, weights, a, b);
}

// round 5
// speedup vs baseline: 1.0667x; 1.0667x over previous
#include <cuda_runtime.h>

// ---- packed f32x2 helpers (sm_103a FFMA2 — only reachable via PTX) ----
__device__ __forceinline__ unsigned long long pack2(float lo, float hi) {
    unsigned long long r;
    asm("mov.b64 %0, {%1, %2};" : "=l"(r) : "f"(lo), "f"(hi));
    return r;
}
__device__ __forceinline__ void unpack2(unsigned long long v, float& lo, float& hi) {
    asm("mov.b64 {%0, %1}, %2;" : "=f"(lo), "=f"(hi) : "l"(v));
}
__device__ __forceinline__ unsigned long long ffma2(unsigned long long a,
                                                    unsigned long long b,
                                                    unsigned long long c) {
    unsigned long long r;
    asm("fma.rn.f32x2 %0, %1, %2, %3;" : "=l"(r) : "l"(a), "l"(b), "l"(c));
    return r;
}

struct C2 { float r, i; };
__device__ __forceinline__ C2 cmul(C2 a, C2 b) {
    return { a.r * b.r - a.i * b.i, a.r * b.i + a.i * b.r };
}
__device__ __forceinline__ C2 cadd(C2 a, C2 b) { return { a.r + b.r, a.i + b.i }; }

__device__ __forceinline__ void mm2(const C2 A[2][2], const C2 B[2][2], C2 O[2][2]) {
#pragma unroll
    for (int r = 0; r < 2; r++)
#pragma unroll
        for (int c = 0; c < 2; c++)
            O[r][c] = cadd(cmul(A[r][0], B[0][c]), cmul(A[r][1], B[1][c]));
}

// U_layer = RZ(w2) @ RY(w1) @ RX(w0)  — MUFU-cheap (__sincosf), runs per thread
__device__ __forceinline__ void layer_unitary(float w0, float w1, float w2, C2 U[2][2]) {
    float c0, s0, c1, s1, c2, s2;
    __sincosf(0.5f * w0, &s0, &c0);
    __sincosf(0.5f * w1, &s1, &c1);
    __sincosf(0.5f * w2, &s2, &c2);
    C2 rx[2][2] = { { {c0, 0.f}, {0.f, -s0} }, { {0.f, -s0}, {c0, 0.f} } };
    C2 ry[2][2] = { { {c1, 0.f}, {-s1, 0.f} }, { {s1, 0.f}, {c1, 0.f} } };
    C2 rz[2][2] = { { {c2, -s2}, {0.f, 0.f} }, { {0.f, 0.f}, {c2, s2} } };
    C2 t[2][2];
    mm2(ry, rx, t);
    mm2(rz, t, U);
}

// out = ca*cos(x) + cb*sin(x) + bb  with ca = a*alpha, cb = a*beta, bb = b
__device__ __forceinline__ void compute_coefs(const float* __restrict__ weights,
                                              const float* __restrict__ a,
                                              const float* __restrict__ b,
                                              float& ca, float& cb, float& bb) {
    C2 U0[2][2], U1[2][2], U[2][2];
    layer_unitary(__ldg(weights + 0), __ldg(weights + 1), __ldg(weights + 2), U0);
    layer_unitary(__ldg(weights + 3), __ldg(weights + 4), __ldg(weights + 5), U1);
    mm2(U1, U0, U);

    float alpha = (U[0][0].r * U[0][0].r + U[0][0].i * U[0][0].i)
                - (U[1][0].r * U[1][0].r + U[1][0].i * U[1][0].i);
    float beta  = (U[0][0].r * U[0][1].r + U[0][0].i * U[0][1].i)
                - (U[1][0].r * U[1][1].r + U[1][0].i * U[1][1].i);

    float av = __ldg(a);
    ca = av * alpha;
    cb = av * beta;
    bb = __ldg(b);
}

// 2 MUFU per element + 4 FFMA2 per float4 (packed scale-and-bias)
__device__ __forceinline__ float4 eval4(float4 v, unsigned long long ca2,
                                        unsigned long long cb2, unsigned long long bb2) {
    float sx, cx, sy, cy, sz, cz, sw, cw;
    __sincosf(v.x, &sx, &cx);
    __sincosf(v.y, &sy, &cy);
    __sincosf(v.z, &sz, &cz);
    __sincosf(v.w, &sw, &cw);
    unsigned long long r01 = ffma2(ca2, pack2(cx, cy), ffma2(cb2, pack2(sx, sy), bb2));
    unsigned long long r23 = ffma2(ca2, pack2(cz, cw), ffma2(cb2, pack2(sz, sw), bb2));
    float4 o;
    unpack2(r01, o.x, o.y);
    unpack2(r23, o.z, o.w);
    return o;
}

__global__ void __launch_bounds__(256)
qpinn_fused(const float4* __restrict__ x4, float4* __restrict__ out4, int n4,
            const float* __restrict__ x, float* __restrict__ out, int n,
            const float* __restrict__ weights,
            const float* __restrict__ a, const float* __restrict__ b) {
    float ca, cb, bb;
    compute_coefs(weights, a, b, ca, cb, bb);
    const unsigned long long ca2 = pack2(ca, ca);
    const unsigned long long cb2 = pack2(cb, cb);
    const unsigned long long bb2 = pack2(bb, bb);

    const int stride = gridDim.x * blockDim.x;
    int idx = blockIdx.x * blockDim.x + threadIdx.x;

    // Main loop: 8 independent float4 loads front-batched per iteration (MLP=8)
    for (; idx + 7 * stride < n4; idx += 8 * stride) {
        float4 v0 = __ldcs(x4 + idx);
        float4 v1 = __ldcs(x4 + idx + stride);
        float4 v2 = __ldcs(x4 + idx + 2 * stride);
        float4 v3 = __ldcs(x4 + idx + 3 * stride);
        float4 v4 = __ldcs(x4 + idx + 4 * stride);
        float4 v5 = __ldcs(x4 + idx + 5 * stride);
        float4 v6 = __ldcs(x4 + idx + 6 * stride);
        float4 v7 = __ldcs(x4 + idx + 7 * stride);
        __stcs(out4 + idx,              eval4(v0, ca2, cb2, bb2));
        __stcs(out4 + idx + stride,     eval4(v1, ca2, cb2, bb2));
        __stcs(out4 + idx + 2 * stride, eval4(v2, ca2, cb2, bb2));
        __stcs(out4 + idx + 3 * stride, eval4(v3, ca2, cb2, bb2));
        __stcs(out4 + idx + 4 * stride, eval4(v4, ca2, cb2, bb2));
        __stcs(out4 + idx + 5 * stride, eval4(v5, ca2, cb2, bb2));
        __stcs(out4 + idx + 6 * stride, eval4(v6, ca2, cb2, bb2));
        __stcs(out4 + idx + 7 * stride, eval4(v7, ca2, cb2, bb2));
    }
    // Remainder float4s
    for (; idx < n4; idx += stride) {
        __stcs(out4 + idx, eval4(__ldcs(x4 + idx), ca2, cb2, bb2));
    }
    // Scalar tail (n not divisible by 4)
    int tail = n4 * 4 + (blockIdx.x * blockDim.x + threadIdx.x);
    if (tail < n) {
        float s, c;
        __sincosf(__ldcs(x + tail), &s, &c);
        float caf, cbf, bbf, dum;
        unpack2(ca2, caf, dum); unpack2(cb2, cbf, dum); unpack2(bb2, bbf, dum);
        __stcs(out + tail, fmaf(caf, c, fmaf(cbf, s, bbf)));
    }
}

extern "C" void kernel_launch(void* const* d_in, const int* in_sizes, int n_in,
                              void* d_out, int out_size) {
    const float* x       = (const float*)d_in[0];
    const float* weights = (const float*)d_in[1];
    const float* a       = (const float*)d_in[2];
    const float* b       = (const float*)d_in[3];
    float* out = (float*)d_out;

    int n = in_sizes[0];
    int n4 = n / 4;

    const int threads = 256;
    // 2048 blocks * 256 threads * 8 float4 * 4 floats = 16,777,216 = N exactly.
    long long want = ((long long)n4 + threads * 8 - 1) / (threads * 8);
    int blocks = (int)want;
    if (blocks < 1) blocks = 1;
    if (blocks > 65535 * 32) blocks = 65535 * 32;

    qpinn_fused<<<blocks, threads>>>((const float4*)x, (float4*)out, n4,
                                     x, out, n, weights, a, b);
}